// round 12
// baseline (speedup 1.0000x reference)
#include <cuda_runtime.h>
#include <cuda_fp16.h>
#include <cstdint>

#define NB 8
#define TT 256
#define HSZ 1000
#define NIN 400
#define NOUTC 400
#define NPAD 4096
#define KA1 1024
#define KA0 512
#define NCTA 128

// ---------------- device scratch ----------------
__device__ __half g_Xt[NB*(TT+1)*KA0];                // [b][257][512], row0 = zeros
__device__ __half g_W1t[(size_t)NPAD*(2*KA0)];        // [4096][1024] n-major, K-contig, fp16
__device__ __half g_W2t[(size_t)NPAD*(2*KA1)];        // [4096][2048]
__device__ __half g_Ht[2][NB*(TT+1)*KA1];             // [b][257][1024], row0 = hid
__device__ float g_C[2][NB*(TT+1)*HSZ];               // [b][257][1000], row0 = cell
__device__ float g_pre[(size_t)(NB*TT)*NPAD];         // conv1 + b2, quad-permuted cols
__device__ float g_b2p[NPAD];
__device__ unsigned g_bar_cnt;                        // global barrier counter

// ---------------- generic helpers ----------------
__device__ __forceinline__ float sigf(float x){
    float e; asm("ex2.approx.f32 %0, %1;" : "=f"(e) : "f"(x * -1.4426950408889634f));
    float r; asm("rcp.approx.f32 %0, %1;" : "=f"(r) : "f"(1.0f + e));
    return r;
}
__device__ __forceinline__ float tanh_fast(float x){ return 2.0f * sigf(2.0f * x) - 1.0f; }
__device__ __forceinline__ void fma2(unsigned long long &c, const unsigned long long a, const unsigned long long b){
    asm("fma.rn.f32x2 %0, %1, %2, %0;" : "+l"(c) : "l"(a), "l"(b));
}
__device__ __forceinline__ unsigned long long dup2(float x){
    unsigned long long r; asm("mov.b64 %0, {%1, %1};" : "=l"(r) : "f"(x)); return r;
}
__device__ __forceinline__ unsigned long long pack2(float x, float y){
    unsigned long long r; asm("mov.b64 %0, {%1, %2};" : "=l"(r) : "f"(x), "f"(y)); return r;
}
__device__ __forceinline__ float2 unpack2(unsigned long long v){
    float2 r; asm("mov.b64 {%0, %1}, %2;" : "=f"(r.x), "=f"(r.y) : "l"(v)); return r;
}
__device__ __forceinline__ float4 ldcg4(const void* p){
    union { uint4 u; float4 f; } t;
    t.u = __ldcg((const uint4*)p);
    return t.f;
}
__device__ __forceinline__ float half_cg(const __half* p){
    return __half2float(__ushort_as_half(__ldcg((const unsigned short*)p)));
}

// grid-wide barrier: all 128 CTAs resident (1 wave). step is monotonic per run.
__device__ __forceinline__ void grid_bar(int step){
    __syncthreads();
    if (threadIdx.x == 0) {
        __threadfence();
        atomicAdd(&g_bar_cnt, 1u);
        const unsigned target = (unsigned)NCTA * (unsigned)step;
        while (*((volatile unsigned*)&g_bar_cnt) < target) {}
        __threadfence();
    }
    __syncthreads();
}

// output copies (shared by both arch paths); reads via L2 (__ldcg)
__device__ void do_copy_slice(float* dst, int hsel, int bstride, int gtid, int GT){
    const int total = NB*TT*NOUTC;
    for (int idx = gtid; idx < total; idx += GT) {
        int c = idx % NOUTC;
        int t = (idx / NOUTC) & 255;
        int b = idx / (NOUTC*TT);
        size_t o = (size_t)(b*(TT+1) + t + 1)*KA1 + (HSZ - NOUTC) + c;
        dst[b*bstride + t*NOUTC + c] = half_cg(&g_Ht[hsel][o]);
    }
}
__device__ void do_copy_last(float* dh, float* dc, int hsel, int gtid, int GT){
    for (int idx = gtid; idx < NB*HSZ; idx += GT) {
        int b = idx / HSZ, h = idx % HSZ;
        size_t oh = (size_t)(b*(TT+1) + TT)*KA1 + h;
        size_t oc = (size_t)(b*(TT+1) + TT)*HSZ + h;
        dh[idx] = half_cg(&g_Ht[hsel][oh]);
        dc[idx] = __ldcg(&g_C[hsel][oc]);
    }
}

#if defined(__CUDA_ARCH_FEAT_SM103_ALL)
// ---------------- tcgen05 helpers (sm_103a cubin pass only) ----------------
__device__ __forceinline__ uint32_t smem_u32(const void* p){
    uint32_t a; asm("{ .reg .u64 t; cvta.to.shared.u64 t, %1; cvt.u32.u64 %0, t; }" : "=r"(a) : "l"(p));
    return a;
}
#define MBAR_INIT(a, c) asm volatile("mbarrier.init.shared.b64 [%0], %1;" :: "r"(a), "r"(c) : "memory")
#define MBAR_ARRIVE(a)  asm volatile("mbarrier.arrive.shared.b64 _, [%0];" :: "r"((uint32_t)(a)) : "memory")
#define MBAR_WAIT(a, ph) do { \
    uint32_t _m=(uint32_t)(a), _p=(uint32_t)(ph), _d; \
    asm volatile("{ .reg .pred p; mbarrier.try_wait.parity.acquire.cta.shared::cta.b64 p, [%1], %2; selp.b32 %0,1,0,p; }" \
        : "=r"(_d) : "r"(_m), "r"(_p) : "memory"); \
    if(!_d){ asm volatile("{ .reg .pred P1; WL_%=: mbarrier.try_wait.parity.acquire.cta.shared::cta.b64 P1, [%0], %1, 0x989680; @P1 bra.uni WD_%=; bra.uni WL_%=; WD_%=: }" \
        :: "r"(_m), "r"(_p) : "memory"); } } while(0)
#define TC_ALLOC(sa, n)  asm volatile("tcgen05.alloc.cta_group::1.sync.aligned.shared::cta.b32 [%0], %1;" :: "r"((uint32_t)(sa)), "r"((uint32_t)(n)) : "memory")
#define TC_DEALLOC(t, n) asm volatile("tcgen05.dealloc.cta_group::1.sync.aligned.b32 %0, %1;" :: "r"(t), "r"(n))
#define TC_COMMIT(a)     asm volatile("tcgen05.commit.cta_group::1.mbarrier::arrive::one.shared::cluster.b64 [%0];" :: "r"((uint32_t)(a)) : "memory")
#define TC_FENCE_AFTER() asm volatile("tcgen05.fence::after_thread_sync;" ::: "memory")
#define TC_WAIT_LD()     asm volatile("tcgen05.wait::ld.sync.aligned;" ::: "memory")
#define FENCE_ASYNC()    asm volatile("fence.proxy.async.shared::cta;" ::: "memory")
#define TC_LD_X32(r, a) \
    asm volatile("tcgen05.ld.sync.aligned.32x32b.x32.b32 " \
        "{%0,%1,%2,%3,%4,%5,%6,%7,%8,%9,%10,%11,%12,%13,%14,%15," \
        "%16,%17,%18,%19,%20,%21,%22,%23,%24,%25,%26,%27,%28,%29,%30,%31}, [%32];" \
        : "=r"((r)[0]),"=r"((r)[1]),"=r"((r)[2]),"=r"((r)[3]),"=r"((r)[4]),"=r"((r)[5]),"=r"((r)[6]),"=r"((r)[7]), \
          "=r"((r)[8]),"=r"((r)[9]),"=r"((r)[10]),"=r"((r)[11]),"=r"((r)[12]),"=r"((r)[13]),"=r"((r)[14]),"=r"((r)[15]), \
          "=r"((r)[16]),"=r"((r)[17]),"=r"((r)[18]),"=r"((r)[19]),"=r"((r)[20]),"=r"((r)[21]),"=r"((r)[22]),"=r"((r)[23]), \
          "=r"((r)[24]),"=r"((r)[25]),"=r"((r)[26]),"=r"((r)[27]),"=r"((r)[28]),"=r"((r)[29]),"=r"((r)[30]),"=r"((r)[31]) \
        : "r"(a))

__device__ __forceinline__ void mma_f16_ss(uint32_t d, uint64_t ad, uint64_t bd, uint32_t idesc, uint32_t en){
    asm volatile(
      "{\n\t.reg .pred p;\n\tsetp.ne.u32 p, %5, 0;\n\t"
      "tcgen05.mma.cta_group::1.kind::f16 [%0], %1, %2, %3, {%4, %4, %4, %4}, p;\n\t}"
      :: "r"(d), "l"(ad), "l"(bd), "r"(idesc), "r"(0u), "r"(en) : "memory");
}
__device__ __forceinline__ uint64_t make_desc64(uint32_t addr){
    return (((uint64_t)4<<61) | ((uint64_t)1<<46) | ((uint64_t)32<<32) | ((uint64_t)1<<16))
         | ((uint64_t)(addr>>4) & 0x3FFF);
}
static constexpr uint32_t IDESC = (1u<<4)|((256u/8)<<17)|((128u/16)<<24);
#endif

// ---------------- prep kernels (3 launches) ----------------
__global__ void k_prep_xb2(const float* __restrict__ X, const float* __restrict__ b2){
    int idx = blockIdx.x * blockDim.x + threadIdx.x;
    if (idx == 0) g_bar_cnt = 0;
    const int totX = NB*(TT+1)*KA0;
    if (idx < totX) {
        int k = idx % KA0;
        int r = (idx / KA0) % (TT+1);
        int b = idx / (KA0*(TT+1));
        float v = 0.0f;
        if (k < NIN && r > 0) v = X[(b*NIN + k)*TT + (r-1)];
        g_Xt[idx] = __float2half(v);
    } else {
        int c = idx - totX;
        if (c < NPAD) {
            float v = 0.0f;
            if (c < 4*HSZ) { int unit = c >> 2, g = c & 3; v = b2[g*HSZ + unit]; }
            g_b2p[c] = v;
        }
    }
}
__global__ void k_prep_w(const float* __restrict__ w1, const float* __restrict__ w2){
    size_t idx = (size_t)blockIdx.x * blockDim.x + threadIdx.x;
    const size_t tot1 = (size_t)NPAD*(2*KA0);
    const size_t tot2 = (size_t)NPAD*(2*KA1);
    if (idx < tot1) {
        int k = (int)(idx % (2*KA0));
        int n = (int)(idx / (2*KA0));
        float v = 0.0f;
        if (n < 4*HSZ) {
            int unit = n >> 2, g = n & 3;
            int ch = g*HSZ + unit;
            int tap = (k >= KA0) ? 1 : 0;
            int kk = k - tap*KA0;
            if (kk < NIN) v = w1[((size_t)ch*NIN + kk)*2 + tap];
        }
        g_W1t[idx] = __float2half(v);
    } else if (idx < tot1 + tot2) {
        size_t j = idx - tot1;
        int k = (int)(j % (2*KA1));
        int n = (int)(j / (2*KA1));
        float v = 0.0f;
        if (n < 4*HSZ) {
            int unit = n >> 2, g = n & 3;
            int ch = g*HSZ + unit;
            int tap = (k >= KA1) ? 1 : 0;
            int kk = k - tap*KA1;
            if (kk < HSZ) v = w2[((size_t)ch*HSZ + kk)*2 + tap];
        }
        g_W2t[j] = __float2half(v);
    }
}
__global__ void k_prep_hc(const float* __restrict__ hid, const float* __restrict__ cell){
    int idx = blockIdx.x * blockDim.x + threadIdx.x;
    const int totH = NB*(TT+1)*KA1;
    if (idx < totH) {
        int k = idx % KA1;
        int r = (idx / KA1) % (TT+1);
        int b = idx / (KA1*(TT+1));
        float v = 0.0f;
        if (r == 0 && k < HSZ) v = hid[b*HSZ + k];
        __half hv = __float2half(v);
        g_Ht[0][idx] = hv; g_Ht[1][idx] = hv;
    } else {
        int j = idx - totH;
        const int totC = NB*(TT+1)*HSZ;
        if (j < totC) {
            int k = j % HSZ;
            int r = (j / HSZ) % (TT+1);
            int b = j / (HSZ*(TT+1));
            float v = (r == 0) ? cell[b*HSZ + k] : 0.0f;
            g_C[0][j] = v; g_C[1][j] = v;
        }
    }
}

// ---------------- persistent fused kernel: pre-GEMM + 40 levels + copies ----------------
// Warp-specialized per CTA (warps 0-7 produce, warp 8 issues MMAs); global
// software barrier between levels (128 CTAs = exactly 1 wave).
#define STG 32768
#define NSTG 6
#define SMEM_DYN (1024 + NSTG*STG)
#define NTHR 288

__global__ __launch_bounds__(NTHR, 1)
void k_persist(float* __restrict__ out)
{
    extern __shared__ __align__(1024) char smem[];

    const int tid = threadIdx.x;
    const int wid = tid >> 5;
    const int lane = tid & 31;
    const int n0 = blockIdx.x * 256;
    const int j  = blockIdx.y;
    const int gtid = (blockIdx.y * gridDim.x + blockIdx.x) * NTHR + tid;
    const int GT = NCTA * NTHR;

    const int OFF_HT  = NB*TT*NOUTC;
    const int OFF_CT  = OFF_HT + NB*HSZ;
    const int OFF_AUX = OFF_CT + NB*HSZ;

#if defined(__CUDA_ARCH_FEAT_SM103_ALL)
    // ======================= tcgen05 path =======================
    const uint32_t sb = smem_u32(smem);

    if (wid == 0) TC_ALLOC(sb, 512);
    if (tid == 0) {
        #pragma unroll
        for (int s = 0; s < NSTG; s++) {
            MBAR_INIT(sb + 64 + 8*s, 256);      // full[s]
            MBAR_INIT(sb + 128 + 8*s, 1);       // done[s]
        }
    }
    __syncthreads();
    const uint32_t tmem = *(volatile uint32_t*)smem;

    int gch = 0;     // global chunk counter (drives stage index + phases)
    int step = 0;    // global barrier step
    int prev = 0;

    for (int lvl = -1; lvl < 40; lvl++) {
        const int mode = (lvl >= 0);
        const int cur = mode ? (prev ^ 1) : 0;
        const __half* __restrict__ Aw;
        const __half* __restrict__ Bw;
        int lda, kw, csec;
        if (mode) { Aw = g_Ht[prev]; Bw = g_W2t; lda = KA1; kw = 2*KA1; csec = 32; }
        else      { Aw = g_Xt;       Bw = g_W1t; lda = KA0; kw = 2*KA0; csec = 16; }
        const int nch = 2 * csec;

        if (tid < 256) {
            // ---------------- producers ----------------
            auto ldgc = [&](int c, float4 (&ra)[4], float4 (&rb)[4]) {
                const int sec = (c >= csec) ? 1 : 0;
                const int kc = (c - sec*csec) << 5;
                const int kb = sec*lda + kc;
                const size_t arow0 = (size_t)(j*(TT+1) + sec);
                #pragma unroll
                for (int it = 0; it < 4; it++) {
                    const int jA = tid + (it << 8);
                    const int row = jA >> 2, f = jA & 3;
                    ra[it] = ldcg4(Aw + (arow0 + row)*lda + kc + (f << 3));
                }
                #pragma unroll
                for (int it = 0; it < 4; it++) {
                    const int jB = tid + (it << 8);
                    const int row = jB >> 2, f = jB & 3;
                    rb[it] = *(const float4*)(Bw + (size_t)(n0 + row)*kw + kb + (f << 3));
                }
            };
            auto stsc = [&](int c, const float4 (&ra)[4], const float4 (&rb)[4]) {
                const int g = gch + c;
                const int u = g / NSTG;
                const int s = g - u*NSTG;
                if (g >= NSTG) MBAR_WAIT(sb + 128 + 8*s, (u - 1) & 1);
                const uint32_t sbase = 1024 + s*STG;
                #pragma unroll
                for (int it = 0; it < 4; it++) {
                    const int jA = tid + (it << 8);
                    const int row = jA >> 2, f = jA & 3;
                    uint32_t off = (uint32_t)(((row >> 3) << 9) + ((row & 7) << 6) + (f << 4));
                    off ^= (off >> 3) & 0x30;
                    *(float4*)(smem + sbase + off) = ra[it];
                }
                #pragma unroll
                for (int it = 0; it < 4; it++) {
                    const int jB = tid + (it << 8);
                    const int row = jB >> 2, f = jB & 3;
                    uint32_t off = (uint32_t)(((row >> 3) << 9) + ((row & 7) << 6) + (f << 4));
                    off ^= (off >> 3) & 0x30;
                    *(float4*)(smem + sbase + 16384 + off) = rb[it];
                }
                FENCE_ASYNC();
                MBAR_ARRIVE(sb + 64 + 8*s);
            };

            float4 raA[4], rbA[4], raB[4], rbB[4];
            ldgc(0, raA, rbA);
            for (int c = 0; c < nch; c += 2) {
                ldgc(c + 1, raB, rbB);
                stsc(c, raA, rbA);
                if (c + 2 < nch) ldgc(c + 2, raA, rbA);
                stsc(c + 1, raB, rbB);
            }
        } else if (tid == 256) {
            // ---------------- dedicated MMA issuer ----------------
            for (int c = 0; c < nch; c++) {
                const int g = gch + c;
                const int u = g / NSTG;
                const int s = g - u*NSTG;
                MBAR_WAIT(sb + 64 + 8*s, u & 1);
                const uint32_t sbase = 1024 + s*STG;
                const uint64_t ad = make_desc64(sb + sbase);
                const uint64_t bd = make_desc64(sb + sbase + 16384);
                #pragma unroll
                for (int h = 0; h < 2; h++) {
                    const uint32_t dt = tmem + h*256;
                    const uint64_t ho = h*512;
                    #pragma unroll
                    for (int k = 0; k < 2; k++)
                        mma_f16_ss(dt, ad + ho + 2*k, bd + 2*k, IDESC, !(c == 0 && k == 0));
                }
                TC_COMMIT(sb + 128 + 8*s);
            }
        }

        // ---- wait for the final commit of this level (completes all MMAs) ----
        {
            const int gl = gch + nch - 1;
            const int ul = gl / NSTG;
            const int sl = gl - ul*NSTG;
            MBAR_WAIT(sb + 128 + 8*sl, ul & 1);
        }
        TC_FENCE_AFTER();

        // ---- epilogue (warps 0-7) ----
        if (tid < 256) {
            const int half = wid >> 2;
            const int mg = j*256 + half*128 + ((wid & 3) << 5) + lane;
            const uint32_t tbase = tmem + half*256;
            if (!mode) {
                float* dst = g_pre + (size_t)mg * NPAD + n0;
                const float* bp = g_b2p + n0;
                #pragma unroll
                for (int nb = 0; nb < 8; nb++) {
                    uint32_t d[32];
                    TC_LD_X32(d, tbase + nb*32);
                    TC_WAIT_LD();
                    #pragma unroll
                    for (int q = 0; q < 8; q++) {
                        const float4 bv = *(const float4*)(bp + nb*32 + q*4);
                        float4 o;
                        o.x = __uint_as_float(d[q*4+0]) + bv.x;
                        o.y = __uint_as_float(d[q*4+1]) + bv.y;
                        o.z = __uint_as_float(d[q*4+2]) + bv.z;
                        o.w = __uint_as_float(d[q*4+3]) + bv.w;
                        *(float4*)(dst + nb*32 + q*4) = o;
                    }
                }
            } else {
                const int trow = mg & 255;
                const int bx = mg >> 8;
                const size_t crow = (size_t)(bx*(TT+1) + trow) * HSZ;
                const size_t hrow = (size_t)(bx*(TT+1) + trow + 1) * KA1;
                const float* __restrict__ Cpv = g_C[prev];
                float* __restrict__ Cnv = g_C[cur];
                __half* __restrict__ Hv = g_Ht[cur];
                const float* prow = g_pre + (size_t)mg * NPAD + n0;
                #pragma unroll
                for (int nb = 0; nb < 8; nb++) {
                    const int col0 = n0 + nb*32;
                    if (col0 >= 4*HSZ) continue;    // uniform across warp
                    uint32_t d[32];
                    TC_LD_X32(d, tbase + nb*32);
                    TC_WAIT_LD();
                    const int np0 = col0 >> 2;
                    const float4* pr = (const float4*)(prow + nb*32);
                    const float* cp = Cpv + crow + np0;
                    float cbuf[8];
                    union { __half b[8]; uint4 u; } Uh;
                    #pragma unroll
                    for (int q = 0; q < 8; q++) {
                        float4 p = pr[q];
                        float cpl = __ldcg(cp + q);
                        float iv = __uint_as_float(d[q*4+0]) + p.x;
                        float ov = __uint_as_float(d[q*4+1]) + p.y;
                        float gv = __uint_as_float(d[q*4+2]) + p.z;
                        float fv = __uint_as_float(d[q*4+3]) + p.w;
                        float cc = sigf(fv)*cpl + sigf(iv)*tanh_fast(gv);
                        float h  = sigf(ov)*tanh_fast(cc);
                        cbuf[q] = cc;
                        Uh.b[q] = __float2half(h);
                    }
                    *(float4*)(Cnv + crow + HSZ + np0)     = make_float4(cbuf[0], cbuf[1], cbuf[2], cbuf[3]);
                    *(float4*)(Cnv + crow + HSZ + np0 + 4) = make_float4(cbuf[4], cbuf[5], cbuf[6], cbuf[7]);
                    *(uint4*)(Hv + hrow + np0) = Uh.u;
                }
            }
        }

        grid_bar(++step);

        if (lvl == 19) {
            do_copy_slice(out + OFF_AUX, cur, 2*TT*NOUTC, gtid, GT);
        }
        if (lvl == 39) {
            do_copy_slice(out, cur, TT*NOUTC, gtid, GT);
            do_copy_slice(out + OFF_AUX + TT*NOUTC, cur, 2*TT*NOUTC, gtid, GT);
            do_copy_last(out + OFF_HT, out + OFF_CT, cur, gtid, GT);
        }

        gch += nch;
        if (mode) prev = cur;
    }

    __syncthreads();
    if (wid == 0) TC_DEALLOC(tmem, 512);

#else
    // ======================= FFMA2 fallback (compute_103 PTX pass) =======================
    const int tidm = tid & 255;
    float* As = (float*)(smem + 1024);
    float* Bs = (float*)(smem + 1024 + 16896);

    const int tx = tidm & 15;
    const int ty = tidm >> 4;
    const int l_row = tidm >> 1;
    const int l_k8  = (tidm & 1) << 3;

    int step = 0;
    int prev = 0;
    for (int lvl = -1; lvl < 40; lvl++) {
        const int mode = (lvl >= 0);
        const int cur = mode ? (prev ^ 1) : 0;
        const __half* __restrict__ Aw;
        const __half* __restrict__ Bw;
        int lda, kw;
        if (mode) { Aw = g_Ht[prev]; Bw = g_W2t; lda = KA1; kw = 2*KA1; }
        else      { Aw = g_Xt;       Bw = g_W1t; lda = KA0; kw = 2*KA0; }
        const int Ktot = 2*lda;
        const int nK = Ktot / 16;

        for (int mh = 0; mh < 2; mh++) {
            const int m0 = j*256 + mh*128;
            const int bidx = j;
            const int trow0 = mh*128;
            for (int npass = 0; npass < 2; npass++) {
                const int n0p = n0 + npass * 128;
                __syncthreads();

                unsigned long long acc[8][4];
                #pragma unroll
                for (int i = 0; i < 8; i++)
                    #pragma unroll
                    for (int jq = 0; jq < 4; jq++) acc[i][jq] = 0ull;

                float fa[8], fb[8];
                {
                    const size_t arow = (size_t)(bidx*(TT+1) + trow0 + l_row);
                    union { uint4 u; __half b[8]; } Aa, Bb2;
                    Aa.u = __ldcg((const uint4*)(Aw + arow*lda + l_k8));
                    #pragma unroll
                    for (int jq = 0; jq < 8; jq++) fa[jq] = __half2float(Aa.b[jq]);
                    Bb2.u = *(const uint4*)(Bw + (size_t)(n0p + l_row)*kw + l_k8);
                    #pragma unroll
                    for (int jq = 0; jq < 8; jq++) fb[jq] = __half2float(Bb2.b[jq]);
                }
                #pragma unroll
                for (int jq = 0; jq < 8; jq++) { As[(l_k8+jq)*132 + l_row] = fa[jq]; Bs[(l_k8+jq)*128 + l_row] = fb[jq]; }
                __syncthreads();

                int buf = 0;
                for (int ks = 0; ks < nK; ks++) {
                    if (ks + 1 < nK) {
                        const int kg = (ks + 1) * 16;
                        const int tap = (kg >= lda) ? 1 : 0;
                        const int kc = kg - tap*lda;
                        const size_t arow = (size_t)(bidx*(TT+1) + trow0 + tap + l_row);
                        union { uint4 u; __half b[8]; } Aa, Bb2;
                        Aa.u = __ldcg((const uint4*)(Aw + arow*lda + kc + l_k8));
                        #pragma unroll
                        for (int jq = 0; jq < 8; jq++) fa[jq] = __half2float(Aa.b[jq]);
                        Bb2.u = *(const uint4*)(Bw + (size_t)(n0p + l_row)*kw + kg + l_k8);
                        #pragma unroll
                        for (int jq = 0; jq < 8; jq++) fb[jq] = __half2float(Bb2.b[jq]);
                    }
                    const float* Ab = As + buf*2112;
                    const float* Bb = Bs + buf*2048;
                    #pragma unroll
                    for (int kk = 0; kk < 16; kk++) {
                        const float4 a0 = *(const float4*)(Ab + kk*132 + ty*8);
                        const float4 a1 = *(const float4*)(Ab + kk*132 + ty*8 + 4);
                        const float4 b0 = *(const float4*)(Bb + kk*128 + tx*8);
                        const float4 b1 = *(const float4*)(Bb + kk*128 + tx*8 + 4);
                        const unsigned long long bb0 = pack2(b0.x, b0.y);
                        const unsigned long long bb1 = pack2(b0.z, b0.w);
                        const unsigned long long bb2 = pack2(b1.x, b1.y);
                        const unsigned long long bb3 = pack2(b1.z, b1.w);
                        const float av[8] = {a0.x,a0.y,a0.z,a0.w,a1.x,a1.y,a1.z,a1.w};
                        #pragma unroll
                        for (int i = 0; i < 8; i++) {
                            const unsigned long long ad = dup2(av[i]);
                            fma2(acc[i][0], ad, bb0);
                            fma2(acc[i][1], ad, bb1);
                            fma2(acc[i][2], ad, bb2);
                            fma2(acc[i][3], ad, bb3);
                        }
                    }
                    if (ks + 1 < nK) {
                        const int nb = buf ^ 1;
                        __syncthreads();
                        #pragma unroll
                        for (int jq = 0; jq < 8; jq++) { As[nb*2112 + (l_k8+jq)*132 + l_row] = fa[jq]; Bs[nb*2048 + (l_k8+jq)*128 + l_row] = fb[jq]; }
                        __syncthreads();
                        buf = nb;
                    }
                }

                if (!mode) {
                    #pragma unroll
                    for (int i = 0; i < 8; i++) {
                        const int mg = m0 + ty*8 + i;
                        float* dst = g_pre + (size_t)mg * NPAD + n0p + tx*8;
                        const float* bb = g_b2p + n0p + tx*8;
                        const float2 v0 = unpack2(acc[i][0]);
                        const float2 v1 = unpack2(acc[i][1]);
                        const float2 v2 = unpack2(acc[i][2]);
                        const float2 v3 = unpack2(acc[i][3]);
                        *(float4*)dst       = make_float4(v0.x + bb[0], v0.y + bb[1], v1.x + bb[2], v1.y + bb[3]);
                        *(float4*)(dst + 4) = make_float4(v2.x + bb[4], v2.y + bb[5], v3.x + bb[6], v3.y + bb[7]);
                    }
                } else {
                    const float* __restrict__ Cpv = g_C[prev];
                    float* __restrict__ Cnv = g_C[cur];
                    __half* __restrict__ Hv = g_Ht[cur];
                    #pragma unroll
                    for (int i = 0; i < 8; i++) {
                        const int mg = m0 + ty*8 + i;
                        const int trow = mg & 255;
                        const int bx = mg >> 8;
                        const float* prow = g_pre + (size_t)mg * NPAD + n0p + tx*8;
                        const float4 p0 = *(const float4*)prow;
                        const float4 p1 = *(const float4*)(prow + 4);
                        #pragma unroll
                        for (int q = 0; q < 2; q++) {
                            const int col = n0p + tx*8 + q*4;
                            if (col < 4*HSZ) {
                                const float2 va = unpack2(acc[i][2*q]);
                                const float2 vb = unpack2(acc[i][2*q + 1]);
                                const float4 p = q ? p1 : p0;
                                const float iv = va.x + p.x;
                                const float ov = va.y + p.y;
                                const float gv = vb.x + p.z;
                                const float fv = vb.y + p.w;
                                const int np = col >> 2;
                                const size_t crow = (size_t)(bx*(TT+1) + trow) * HSZ + np;
                                const float cc = sigf(fv)*__ldcg(&Cpv[crow]) + sigf(iv)*tanh_fast(gv);
                                const float h  = sigf(ov)*tanh_fast(cc);
                                Cnv[crow + HSZ] = cc;
                                const size_t ho = (size_t)(bx*(TT+1) + trow + 1) * KA1 + np;
                                Hv[ho] = __float2half(h);
                            }
                        }
                    }
                }
            }
        }

        grid_bar(++step);
        if (lvl == 19) {
            do_copy_slice(out + OFF_AUX, cur, 2*TT*NOUTC, gtid, GT);
        }
        if (lvl == 39) {
            do_copy_slice(out, cur, TT*NOUTC, gtid, GT);
            do_copy_slice(out + OFF_AUX + TT*NOUTC, cur, 2*TT*NOUTC, gtid, GT);
            do_copy_last(out + OFF_HT, out + OFF_CT, cur, gtid, GT);
        }
        if (mode) prev = cur;
    }
#endif
}

// ---------------- launch ----------------
extern "C" void kernel_launch(void* const* d_in, const int* in_sizes, int n_in,
                              void* d_out, int out_size)
{
    const float* X    = (const float*)d_in[0];
    const float* hid  = (const float*)d_in[1];
    const float* cell = (const float*)d_in[2];
    const float* w1   = (const float*)d_in[3];
    const float* w2   = (const float*)d_in[4];
    const float* b2   = (const float*)d_in[5];
    float* out = (float*)d_out;

    cudaFuncSetAttribute(k_persist, cudaFuncAttributeMaxDynamicSharedMemorySize, SMEM_DYN);

    k_prep_xb2<<<(NB*(TT+1)*KA0 + NPAD + 255)/256, 256>>>(X, b2);
    k_prep_w  <<<(int)(((size_t)NPAD*(2*KA0 + 2*KA1) + 255)/256), 256>>>(w1, w2);
    k_prep_hc <<<(NB*(TT+1)*KA1 + NB*(TT+1)*HSZ + 255)/256, 256>>>(hid, cell);

    dim3 grid(NPAD/256, NB);   // 16 x 8 = 128 CTAs = exactly 1 wave
    k_persist<<<grid, NTHR, SMEM_DYN>>>(out);
}

// round 13
// speedup vs baseline: 1.2104x; 1.2104x over previous
#include <cuda_runtime.h>
#include <cuda_fp16.h>
#include <cstdint>

#define NB 8
#define TT 256
#define HSZ 1000
#define NIN 400
#define NOUTC 400
#define NPAD 4096
#define KA1 1024
#define KA0 512

// ---------------- device scratch ----------------
__device__ __half g_Xt[NB*(TT+1)*KA0];                // [b][257][512], row0 = zeros
__device__ __half g_W1t[(size_t)NPAD*(2*KA0)];        // [4096][1024] n-major, K-contig, fp16
__device__ __half g_W2t[(size_t)NPAD*(2*KA1)];        // [4096][2048]
__device__ __half g_Ht[2][NB*(TT+1)*KA1];             // [b][257][1024], row0 = hid
__device__ float g_C[2][NB*(TT+1)*HSZ];               // [b][257][1000], row0 = cell
__device__ float g_pre[(size_t)(NB*TT)*NPAD];         // conv1 + b2, quad-permuted cols
__device__ float g_b2p[NPAD];

// ---------------- generic helpers ----------------
__device__ __forceinline__ float sigf(float x){
    float e; asm("ex2.approx.f32 %0, %1;" : "=f"(e) : "f"(x * -1.4426950408889634f));
    float r; asm("rcp.approx.f32 %0, %1;" : "=f"(r) : "f"(1.0f + e));
    return r;
}
__device__ __forceinline__ float tanh_fast(float x){ return 2.0f * sigf(2.0f * x) - 1.0f; }
// f32x2 packed-FMA helpers (fallback path)
__device__ __forceinline__ void fma2(unsigned long long &c, const unsigned long long a, const unsigned long long b){
    asm("fma.rn.f32x2 %0, %1, %2, %0;" : "+l"(c) : "l"(a), "l"(b));
}
__device__ __forceinline__ unsigned long long dup2(float x){
    unsigned long long r; asm("mov.b64 %0, {%1, %1};" : "=l"(r) : "f"(x)); return r;
}
__device__ __forceinline__ unsigned long long pack2(float x, float y){
    unsigned long long r; asm("mov.b64 %0, {%1, %2};" : "=l"(r) : "f"(x), "f"(y)); return r;
}
__device__ __forceinline__ float2 unpack2(unsigned long long v){
    float2 r; asm("mov.b64 {%0, %1}, %2;" : "=f"(r.x), "=f"(r.y) : "l"(v)); return r;
}

#if defined(__CUDA_ARCH_FEAT_SM103_ALL)
// ---------------- tcgen05 helpers (sm_103a cubin pass only) ----------------
__device__ __forceinline__ uint32_t smem_u32(const void* p){
    uint32_t a; asm("{ .reg .u64 t; cvta.to.shared.u64 t, %1; cvt.u32.u64 %0, t; }" : "=r"(a) : "l"(p));
    return a;
}
#define MBAR_INIT(a, c) asm volatile("mbarrier.init.shared.b64 [%0], %1;" :: "r"(a), "r"(c) : "memory")
#define MBAR_ARRIVE(a)  asm volatile("mbarrier.arrive.shared.b64 _, [%0];" :: "r"((uint32_t)(a)) : "memory")
#define MBAR_WAIT(a, ph) do { \
    uint32_t _m=(uint32_t)(a), _p=(uint32_t)(ph), _d; \
    asm volatile("{ .reg .pred p; mbarrier.try_wait.parity.acquire.cta.shared::cta.b64 p, [%1], %2; selp.b32 %0,1,0,p; }" \
        : "=r"(_d) : "r"(_m), "r"(_p) : "memory"); \
    if(!_d){ asm volatile("{ .reg .pred P1; WL_%=: mbarrier.try_wait.parity.acquire.cta.shared::cta.b64 P1, [%0], %1, 0x989680; @P1 bra.uni WD_%=; bra.uni WL_%=; WD_%=: }" \
        :: "r"(_m), "r"(_p) : "memory"); } } while(0)
#define TC_ALLOC(sa, n)  asm volatile("tcgen05.alloc.cta_group::1.sync.aligned.shared::cta.b32 [%0], %1;" :: "r"((uint32_t)(sa)), "r"((uint32_t)(n)) : "memory")
#define TC_DEALLOC(t, n) asm volatile("tcgen05.dealloc.cta_group::1.sync.aligned.b32 %0, %1;" :: "r"(t), "r"(n))
#define TC_COMMIT(a)     asm volatile("tcgen05.commit.cta_group::1.mbarrier::arrive::one.shared::cluster.b64 [%0];" :: "r"((uint32_t)(a)) : "memory")
#define TC_FENCE_AFTER() asm volatile("tcgen05.fence::after_thread_sync;" ::: "memory")
#define TC_WAIT_LD()     asm volatile("tcgen05.wait::ld.sync.aligned;" ::: "memory")
#define FENCE_ASYNC()    asm volatile("fence.proxy.async.shared::cta;" ::: "memory")
#define TC_LD_X32(r, a) \
    asm volatile("tcgen05.ld.sync.aligned.32x32b.x32.b32 " \
        "{%0,%1,%2,%3,%4,%5,%6,%7,%8,%9,%10,%11,%12,%13,%14,%15," \
        "%16,%17,%18,%19,%20,%21,%22,%23,%24,%25,%26,%27,%28,%29,%30,%31}, [%32];" \
        : "=r"((r)[0]),"=r"((r)[1]),"=r"((r)[2]),"=r"((r)[3]),"=r"((r)[4]),"=r"((r)[5]),"=r"((r)[6]),"=r"((r)[7]), \
          "=r"((r)[8]),"=r"((r)[9]),"=r"((r)[10]),"=r"((r)[11]),"=r"((r)[12]),"=r"((r)[13]),"=r"((r)[14]),"=r"((r)[15]), \
          "=r"((r)[16]),"=r"((r)[17]),"=r"((r)[18]),"=r"((r)[19]),"=r"((r)[20]),"=r"((r)[21]),"=r"((r)[22]),"=r"((r)[23]), \
          "=r"((r)[24]),"=r"((r)[25]),"=r"((r)[26]),"=r"((r)[27]),"=r"((r)[28]),"=r"((r)[29]),"=r"((r)[30]),"=r"((r)[31]) \
        : "r"(a))

__device__ __forceinline__ void mma_f16_ss(uint32_t d, uint64_t ad, uint64_t bd, uint32_t idesc, uint32_t en){
    asm volatile(
      "{\n\t.reg .pred p;\n\tsetp.ne.u32 p, %5, 0;\n\t"
      "tcgen05.mma.cta_group::1.kind::f16 [%0], %1, %2, %3, {%4, %4, %4, %4}, p;\n\t}"
      :: "r"(d), "l"(ad), "l"(bd), "r"(idesc), "r"(0u), "r"(en) : "memory");
}
// SW128 K-major descriptor: layout=2, version=1, SBO=64 (1024B 8-row group), LBO=1 (16B)
__device__ __forceinline__ uint64_t make_desc128(uint32_t addr){
    return (((uint64_t)2<<61) | ((uint64_t)1<<46) | ((uint64_t)64<<32) | ((uint64_t)1<<16))
         | ((uint64_t)(addr>>4) & 0x3FFF);
}
// cg1 f16: dtype=F32, a/b = F16 (0), M=128, N=256
static constexpr uint32_t IDESC = (1u<<4)|((256u/8)<<17)|((128u/16)<<24);
#endif

// ---------------- prep kernels (3 launches) ----------------
__global__ void k_prep_xb2(const float* __restrict__ X, const float* __restrict__ b2){
    int idx = blockIdx.x * blockDim.x + threadIdx.x;
    const int totX = NB*(TT+1)*KA0;
    if (idx < totX) {
        int k = idx % KA0;
        int r = (idx / KA0) % (TT+1);
        int b = idx / (KA0*(TT+1));
        float v = 0.0f;
        if (k < NIN && r > 0) v = X[(b*NIN + k)*TT + (r-1)];
        g_Xt[idx] = __float2half(v);
    } else {
        int c = idx - totX;
        if (c < NPAD) {
            float v = 0.0f;
            if (c < 4*HSZ) { int unit = c >> 2, g = c & 3; v = b2[g*HSZ + unit]; }
            g_b2p[c] = v;
        }
    }
}
__global__ void k_prep_w(const float* __restrict__ w1, const float* __restrict__ w2){
    size_t idx = (size_t)blockIdx.x * blockDim.x + threadIdx.x;
    const size_t tot1 = (size_t)NPAD*(2*KA0);
    const size_t tot2 = (size_t)NPAD*(2*KA1);
    if (idx < tot1) {
        int k = (int)(idx % (2*KA0));
        int n = (int)(idx / (2*KA0));
        float v = 0.0f;
        if (n < 4*HSZ) {
            int unit = n >> 2, g = n & 3;
            int ch = g*HSZ + unit;
            int tap = (k >= KA0) ? 1 : 0;
            int kk = k - tap*KA0;
            if (kk < NIN) v = w1[((size_t)ch*NIN + kk)*2 + tap];
        }
        g_W1t[idx] = __float2half(v);
    } else if (idx < tot1 + tot2) {
        size_t j = idx - tot1;
        int k = (int)(j % (2*KA1));
        int n = (int)(j / (2*KA1));
        float v = 0.0f;
        if (n < 4*HSZ) {
            int unit = n >> 2, g = n & 3;
            int ch = g*HSZ + unit;
            int tap = (k >= KA1) ? 1 : 0;
            int kk = k - tap*KA1;
            if (kk < HSZ) v = w2[((size_t)ch*HSZ + kk)*2 + tap];
        }
        g_W2t[j] = __float2half(v);
    }
}
__global__ void k_prep_hc(const float* __restrict__ hid, const float* __restrict__ cell){
    int idx = blockIdx.x * blockDim.x + threadIdx.x;
    const int totH = NB*(TT+1)*KA1;
    if (idx < totH) {
        int k = idx % KA1;
        int r = (idx / KA1) % (TT+1);
        int b = idx / (KA1*(TT+1));
        float v = 0.0f;
        if (r == 0 && k < HSZ) v = hid[b*HSZ + k];
        __half hv = __float2half(v);
        g_Ht[0][idx] = hv; g_Ht[1][idx] = hv;
    } else {
        int j = idx - totH;
        const int totC = NB*(TT+1)*HSZ;
        if (j < totC) {
            int k = j % HSZ;
            int r = (j / HSZ) % (TT+1);
            int b = j / (HSZ*(TT+1));
            float v = (r == 0) ? cell[b*HSZ + k] : 0.0f;
            g_C[0][j] = v; g_C[1][j] = v;
        }
    }
}

// ---------------- main fused GEMM + gates (cg1, M=256 x N=256 per CTA) ----------------
// Warp-specialized: 288 threads. Warps 0-7 = producers (LDG->STS->fence->arrive),
// warp 8 (tid 256) = MMA issuer. Single fp16 A/B, fp32 TMEM (two M=128 tiles).
// K-chunk = 64 fp16 (SW128, 4 K-steps/half, 8 dispatches/chunk).
// 3-stage smem pipeline (64KB/stage) + register double-buffer.
#define STG 65536
#define NSTG 3
#define SMEM_DYN (1024 + NSTG*STG)
#define NTHR 288

__global__ __launch_bounds__(NTHR, 1)
void k_tcmm(int mode, int prev, int cur)
{
    extern __shared__ __align__(1024) char smem[];

    const int tid = threadIdx.x;
    const int wid = tid >> 5;
    const int lane = tid & 31;

    const __half* __restrict__ Aw;
    const __half* __restrict__ Bw;
    int lda, kw, csec;
    if (mode) { Aw = g_Ht[prev]; Bw = g_W2t; lda = KA1; kw = 2*KA1; csec = 16; }
    else      { Aw = g_Xt;       Bw = g_W1t; lda = KA0; kw = 2*KA0; csec = 8; }

    const int n0 = blockIdx.x * 256;
    const int j  = blockIdx.y;             // batch index; CTA covers its 256 tokens

#if defined(__CUDA_ARCH_FEAT_SM103_ALL)
    // ======================= tcgen05 path =======================
    const uint32_t sb = smem_u32(smem);

    if (wid == 0) TC_ALLOC(sb, 512);
    if (tid == 0) {
        #pragma unroll
        for (int s = 0; s < NSTG; s++) {
            MBAR_INIT(sb + 64 + 8*s, 256);      // full[s]: all producer STS landed
            MBAR_INIT(sb + 128 + 8*s, 1);       // done[s]: MMA consumed stage
        }
    }
    __syncthreads();
    const uint32_t tmem = *(volatile uint32_t*)smem;

    const int nch = 2 * csec;                // 32 (mode1) or 16 (mode0), even

    if (tid < 256) {
        // ---------------- producers ----------------
        // Per chunk: A 256 rows x 64 halves (8 f4/thread), B 256 rows x 64 halves.
        auto ldgc = [&](int c, float4 (&ra)[8], float4 (&rb)[8]) {
            const int sec = (c >= csec) ? 1 : 0;
            const int kc = (c - sec*csec) << 6;
            const int kb = sec*lda + kc;
            const size_t arow0 = (size_t)(j*(TT+1) + sec);
            #pragma unroll
            for (int it = 0; it < 8; it++) {
                const int jA = tid + (it << 8);
                const int row = jA >> 3, f = jA & 7;
                ra[it] = *(const float4*)(Aw + (arow0 + row)*lda + kc + (f << 3));
            }
            #pragma unroll
            for (int it = 0; it < 8; it++) {
                const int jB = tid + (it << 8);
                const int row = jB >> 3, f = jB & 7;
                rb[it] = *(const float4*)(Bw + (size_t)(n0 + row)*kw + kb + (f << 3));
            }
        };
        auto stsc = [&](int c, const float4 (&ra)[8], const float4 (&rb)[8]) {
            const int u = c / NSTG;
            const int s = c - u*NSTG;
            if (c >= NSTG) MBAR_WAIT(sb + 128 + 8*s, (u - 1) & 1);
            const uint32_t sbase = 1024 + s*STG;
            #pragma unroll
            for (int it = 0; it < 8; it++) {
                const int jA = tid + (it << 8);
                const int row = jA >> 3, f = jA & 7;
                uint32_t off = (uint32_t)((row << 7) + (f << 4));
                off ^= (off >> 3) & 0x70;
                *(float4*)(smem + sbase + off) = ra[it];
            }
            #pragma unroll
            for (int it = 0; it < 8; it++) {
                const int jB = tid + (it << 8);
                const int row = jB >> 3, f = jB & 7;
                uint32_t off = (uint32_t)((row << 7) + (f << 4));
                off ^= (off >> 3) & 0x70;
                *(float4*)(smem + sbase + 32768 + off) = rb[it];
            }
            FENCE_ASYNC();
            MBAR_ARRIVE(sb + 64 + 8*s);
        };

        float4 raA[8], rbA[8], raB[8], rbB[8];
        ldgc(0, raA, rbA);
        for (int c = 0; c < nch; c += 2) {
            ldgc(c + 1, raB, rbB);          // prefetch next chunk before consuming current
            stsc(c, raA, rbA);
            if (c + 2 < nch) ldgc(c + 2, raA, rbA);
            stsc(c + 1, raB, rbB);
        }
    } else if (tid == 256) {
        // ---------------- dedicated MMA issuer ----------------
        for (int c = 0; c < nch; c++) {
            const int u = c / NSTG;
            const int s = c - u*NSTG;
            MBAR_WAIT(sb + 64 + 8*s, u & 1);
            const uint32_t sbase = 1024 + s*STG;
            const uint64_t ad = make_desc128(sb + sbase);
            const uint64_t bd = make_desc128(sb + sbase + 32768);
            #pragma unroll
            for (int h = 0; h < 2; h++) {
                const uint32_t dt = tmem + h*256;
                const uint64_t ho = (uint64_t)h*1024;    // 128 rows x 128B = 1024 x 16B units
                #pragma unroll
                for (int k = 0; k < 4; k++)
                    mma_f16_ss(dt, ad + ho + 2*k, bd + 2*k, IDESC, !(c == 0 && k == 0));
            }
            TC_COMMIT(sb + 128 + 8*s);
        }
    }

    // ---- drain: all threads wait for the last commit of every stage ----
    #pragma unroll
    for (int s = 0; s < NSTG; s++) {
        if (s < nch) {
            const int cl = s + NSTG*((nch - 1 - s)/NSTG);   // last chunk using stage s
            MBAR_WAIT(sb + 128 + 8*s, (cl/NSTG) & 1);
        }
    }
    TC_FENCE_AFTER();

    // ---- epilogue (warps 0-7): warp w -> D-half (w>>2), rows (w&3)*32+lane ----
    if (tid < 256) {
        const int half = wid >> 2;
        const int mg = j*256 + half*128 + ((wid & 3) << 5) + lane;
        const uint32_t tbase = tmem + half*256;
        if (mode == 0) {
            float* dst = g_pre + (size_t)mg * NPAD + n0;
            const float* bp = g_b2p + n0;
            #pragma unroll
            for (int nb = 0; nb < 8; nb++) {
                uint32_t d[32];
                TC_LD_X32(d, tbase + nb*32);
                TC_WAIT_LD();
                #pragma unroll
                for (int q = 0; q < 8; q++) {
                    const float4 bv = *(const float4*)(bp + nb*32 + q*4);
                    float4 o;
                    o.x = __uint_as_float(d[q*4+0]) + bv.x;
                    o.y = __uint_as_float(d[q*4+1]) + bv.y;
                    o.z = __uint_as_float(d[q*4+2]) + bv.z;
                    o.w = __uint_as_float(d[q*4+3]) + bv.w;
                    *(float4*)(dst + nb*32 + q*4) = o;
                }
            }
        } else {
            const int trow = mg & 255;
            const int bx = mg >> 8;
            const size_t crow = (size_t)(bx*(TT+1) + trow) * HSZ;
            const size_t hrow = (size_t)(bx*(TT+1) + trow + 1) * KA1;
            const float* __restrict__ Cpv = g_C[prev];
            float* __restrict__ Cnv = g_C[cur];
            __half* __restrict__ Hv = g_Ht[cur];
            const float* prow = g_pre + (size_t)mg * NPAD + n0;
            #pragma unroll
            for (int nb = 0; nb < 8; nb++) {
                const int col0 = n0 + nb*32;
                if (col0 >= 4*HSZ) continue;    // uniform across warp
                uint32_t d[32];
                TC_LD_X32(d, tbase + nb*32);
                TC_WAIT_LD();
                const int np0 = col0 >> 2;
                const float4* pr = (const float4*)(prow + nb*32);
                const float* cp = Cpv + crow + np0;
                float cbuf[8];
                union { __half b[8]; uint4 u; } Uh;
                #pragma unroll
                for (int q = 0; q < 8; q++) {
                    float4 p = pr[q];
                    float iv = __uint_as_float(d[q*4+0]) + p.x;
                    float ov = __uint_as_float(d[q*4+1]) + p.y;
                    float gv = __uint_as_float(d[q*4+2]) + p.z;
                    float fv = __uint_as_float(d[q*4+3]) + p.w;
                    float cc = sigf(fv)*cp[q] + sigf(iv)*tanh_fast(gv);
                    float h  = sigf(ov)*tanh_fast(cc);
                    cbuf[q] = cc;
                    Uh.b[q] = __float2half(h);
                }
                *(float4*)(Cnv + crow + HSZ + np0)     = make_float4(cbuf[0], cbuf[1], cbuf[2], cbuf[3]);
                *(float4*)(Cnv + crow + HSZ + np0 + 4) = make_float4(cbuf[4], cbuf[5], cbuf[6], cbuf[7]);
                *(uint4*)(Hv + hrow + np0) = Uh.u;
            }
        }
    }
    __syncthreads();
    if (wid == 0) TC_DEALLOC(tmem, 512);

#else
    // ======================= FFMA2 fallback (compute_103 PTX pass) =======================
    const int tidm = tid & 255;
    float* As = (float*)(smem + 1024);            // [2][16][132]
    float* Bs = (float*)(smem + 1024 + 16896);    // [2][16][128]

    const int tx = tidm & 15;
    const int ty = tidm >> 4;
    const int l_row = tidm >> 1;
    const int l_k8  = (tidm & 1) << 3;

    const int Ktot = 2*lda;
    const int nK = Ktot / 16;

    for (int mh = 0; mh < 2; mh++) {
        const int m0 = j*256 + mh*128;
        const int bidx = j;
        const int trow0 = mh*128;
        for (int npass = 0; npass < 2; npass++) {
            const int n0p = n0 + npass * 128;
            __syncthreads();

            unsigned long long acc[8][4];
            #pragma unroll
            for (int i = 0; i < 8; i++)
                #pragma unroll
                for (int jq = 0; jq < 4; jq++) acc[i][jq] = 0ull;

            float fa[8], fb[8];
            {
                const size_t arow = (size_t)(bidx*(TT+1) + trow0 + l_row);
                union { uint4 u; __half b[8]; } Aa, Bb2;
                Aa.u = *(const uint4*)(Aw + arow*lda + l_k8);
                #pragma unroll
                for (int jq = 0; jq < 8; jq++) fa[jq] = __half2float(Aa.b[jq]);
                Bb2.u = *(const uint4*)(Bw + (size_t)(n0p + l_row)*kw + l_k8);
                #pragma unroll
                for (int jq = 0; jq < 8; jq++) fb[jq] = __half2float(Bb2.b[jq]);
            }
            #pragma unroll
            for (int jq = 0; jq < 8; jq++) { As[(l_k8+jq)*132 + l_row] = fa[jq]; Bs[(l_k8+jq)*128 + l_row] = fb[jq]; }
            __syncthreads();

            int buf = 0;
            for (int ks = 0; ks < nK; ks++) {
                if (ks + 1 < nK) {
                    const int kg = (ks + 1) * 16;
                    const int tap = (kg >= lda) ? 1 : 0;
                    const int kc = kg - tap*lda;
                    const size_t arow = (size_t)(bidx*(TT+1) + trow0 + tap + l_row);
                    union { uint4 u; __half b[8]; } Aa, Bb2;
                    Aa.u = *(const uint4*)(Aw + arow*lda + kc + l_k8);
                    #pragma unroll
                    for (int jq = 0; jq < 8; jq++) fa[jq] = __half2float(Aa.b[jq]);
                    Bb2.u = *(const uint4*)(Bw + (size_t)(n0p + l_row)*kw + kg + l_k8);
                    #pragma unroll
                    for (int jq = 0; jq < 8; jq++) fb[jq] = __half2float(Bb2.b[jq]);
                }
                const float* Ab = As + buf*2112;
                const float* Bb = Bs + buf*2048;
                #pragma unroll
                for (int kk = 0; kk < 16; kk++) {
                    const float4 a0 = *(const float4*)(Ab + kk*132 + ty*8);
                    const float4 a1 = *(const float4*)(Ab + kk*132 + ty*8 + 4);
                    const float4 b0 = *(const float4*)(Bb + kk*128 + tx*8);
                    const float4 b1 = *(const float4*)(Bb + kk*128 + tx*8 + 4);
                    const unsigned long long bb0 = pack2(b0.x, b0.y);
                    const unsigned long long bb1 = pack2(b0.z, b0.w);
                    const unsigned long long bb2 = pack2(b1.x, b1.y);
                    const unsigned long long bb3 = pack2(b1.z, b1.w);
                    const float av[8] = {a0.x,a0.y,a0.z,a0.w,a1.x,a1.y,a1.z,a1.w};
                    #pragma unroll
                    for (int i = 0; i < 8; i++) {
                        const unsigned long long ad = dup2(av[i]);
                        fma2(acc[i][0], ad, bb0);
                        fma2(acc[i][1], ad, bb1);
                        fma2(acc[i][2], ad, bb2);
                        fma2(acc[i][3], ad, bb3);
                    }
                }
                if (ks + 1 < nK) {
                    const int nb = buf ^ 1;
                    __syncthreads();
                    #pragma unroll
                    for (int jq = 0; jq < 8; jq++) { As[nb*2112 + (l_k8+jq)*132 + l_row] = fa[jq]; Bs[nb*2048 + (l_k8+jq)*128 + l_row] = fb[jq]; }
                    __syncthreads();
                    buf = nb;
                }
            }

            if (mode == 0) {
                #pragma unroll
                for (int i = 0; i < 8; i++) {
                    const int mg = m0 + ty*8 + i;
                    float* dst = g_pre + (size_t)mg * NPAD + n0p + tx*8;
                    const float* bb = g_b2p + n0p + tx*8;
                    const float2 v0 = unpack2(acc[i][0]);
                    const float2 v1 = unpack2(acc[i][1]);
                    const float2 v2 = unpack2(acc[i][2]);
                    const float2 v3 = unpack2(acc[i][3]);
                    *(float4*)dst       = make_float4(v0.x + bb[0], v0.y + bb[1], v1.x + bb[2], v1.y + bb[3]);
                    *(float4*)(dst + 4) = make_float4(v2.x + bb[4], v2.y + bb[5], v3.x + bb[6], v3.y + bb[7]);
                }
            } else {
                const float* __restrict__ Cpv = g_C[prev];
                float* __restrict__ Cnv = g_C[cur];
                __half* __restrict__ Hv = g_Ht[cur];
                #pragma unroll
                for (int i = 0; i < 8; i++) {
                    const int mg = m0 + ty*8 + i;
                    const int trow = mg & 255;
                    const int bx = mg >> 8;
                    const float* prow = g_pre + (size_t)mg * NPAD + n0p + tx*8;
                    const float4 p0 = *(const float4*)prow;
                    const float4 p1 = *(const float4*)(prow + 4);
                    #pragma unroll
                    for (int q = 0; q < 2; q++) {
                        const int col = n0p + tx*8 + q*4;
                        if (col < 4*HSZ) {
                            const float2 va = unpack2(acc[i][2*q]);
                            const float2 vb = unpack2(acc[i][2*q + 1]);
                            const float4 p = q ? p1 : p0;
                            const float iv = va.x + p.x;
                            const float ov = va.y + p.y;
                            const float gv = vb.x + p.z;
                            const float fv = vb.y + p.w;
                            const int np = col >> 2;
                            const size_t crow = (size_t)(bx*(TT+1) + trow) * HSZ + np;
                            const float cc = sigf(fv)*Cpv[crow] + sigf(iv)*tanh_fast(gv);
                            const float h  = sigf(ov)*tanh_fast(cc);
                            Cnv[crow + HSZ] = cc;
                            const size_t ho = (size_t)(bx*(TT+1) + trow + 1) * KA1 + np;
                            Hv[ho] = __float2half(h);
                        }
                    }
                }
            }
        }
    }
#endif
}

// ---------------- output copies ----------------
__global__ void k_copy_slice(float* __restrict__ dst, int hsel, int bstride){
    int idx = blockIdx.x * blockDim.x + threadIdx.x;
    const int total = NB*TT*NOUTC;
    if (idx >= total) return;
    int c = idx % NOUTC;
    int t = (idx / NOUTC) & 255;
    int b = idx / (NOUTC*TT);
    size_t o = (size_t)(b*(TT+1) + t + 1)*KA1 + (HSZ - NOUTC) + c;
    dst[b*bstride + t*NOUTC + c] = __half2float(g_Ht[hsel][o]);
}
__global__ void k_copy_last(float* __restrict__ dh, float* __restrict__ dc, int hsel){
    int idx = blockIdx.x * blockDim.x + threadIdx.x;
    if (idx >= NB*HSZ) return;
    int b = idx / HSZ, h = idx % HSZ;
    size_t oh = (size_t)(b*(TT+1) + TT)*KA1 + h;
    size_t oc = (size_t)(b*(TT+1) + TT)*HSZ + h;
    dh[idx] = __half2float(g_Ht[hsel][oh]);
    dc[idx] = g_C[hsel][oc];
}

// ---------------- launch ----------------
extern "C" void kernel_launch(void* const* d_in, const int* in_sizes, int n_in,
                              void* d_out, int out_size)
{
    const float* X    = (const float*)d_in[0];
    const float* hid  = (const float*)d_in[1];
    const float* cell = (const float*)d_in[2];
    const float* w1   = (const float*)d_in[3];
    const float* w2   = (const float*)d_in[4];
    const float* b2   = (const float*)d_in[5];
    float* out = (float*)d_out;

    cudaFuncSetAttribute(k_tcmm, cudaFuncAttributeMaxDynamicSharedMemorySize, SMEM_DYN);

    k_prep_xb2<<<(NB*(TT+1)*KA0 + NPAD + 255)/256, 256>>>(X, b2);
    k_prep_w  <<<(int)(((size_t)NPAD*(2*KA0 + 2*KA1) + 255)/256), 256>>>(w1, w2);
    k_prep_hc <<<(NB*(TT+1)*KA1 + NB*(TT+1)*HSZ + 255)/256, 256>>>(hid, cell);

    dim3 grid(NPAD/256, NB);   // 16 x 8 = 128 CTAs, each M=256 x N=256
    k_tcmm<<<grid, NTHR, SMEM_DYN>>>(0, 0, 0);     // pre = conv1 + b2

    const int OFF_HT  = NB*TT*NOUTC;          // 819200
    const int OFF_CT  = OFF_HT + NB*HSZ;      // 827200
    const int OFF_AUX = OFF_CT + NB*HSZ;      // 835200

    int prev = 0;
    for (int i = 0; i < 40; i++) {
        int cur = prev ^ 1;
        k_tcmm<<<grid, NTHR, SMEM_DYN>>>(1, prev, cur);
        if (i == 19) {
            k_copy_slice<<<(NB*TT*NOUTC + 255)/256, 256>>>(out + OFF_AUX, cur, 2*TT*NOUTC);
        }
        if (i == 39) {
            k_copy_slice<<<(NB*TT*NOUTC + 255)/256, 256>>>(out, cur, TT*NOUTC);
            k_copy_slice<<<(NB*TT*NOUTC + 255)/256, 256>>>(out + OFF_AUX + TT*NOUTC, cur, 2*TT*NOUTC);
            k_copy_last <<<(NB*HSZ + 255)/256, 256>>>(out + OFF_HT, out + OFF_CT, cur);
        }
        prev = cur;
    }
}

// round 16
// speedup vs baseline: 1.2144x; 1.0032x over previous
#include <cuda_runtime.h>
#include <cuda_fp16.h>
#include <cstdint>

#define NB 8
#define TT 256
#define HSZ 1000
#define NIN 400
#define NOUTC 400
#define NPAD 4096
#define KA1 1024
#define KA0 512

// ---------------- device scratch ----------------
__device__ __half g_Xt[NB*(TT+1)*KA0];                // [b][257][512], row0 = zeros
__device__ __half g_W1t[(size_t)NPAD*(2*KA0)];        // [4096][1024] n-major, K-contig, fp16
__device__ __half g_W2t[(size_t)NPAD*(2*KA1)];        // [4096][2048]
__device__ __half g_Ht[2][NB*(TT+1)*KA1];             // [b][257][1024], row0 = hid
__device__ float g_C[2][NB*(TT+1)*HSZ];               // [b][257][1000], row0 = cell
__device__ float g_pre[(size_t)(NB*TT)*NPAD];         // conv1 + b2, quad-permuted cols
__device__ float g_b2p[NPAD];

// ---------------- generic helpers ----------------
__device__ __forceinline__ float sigf(float x){
    float e; asm("ex2.approx.f32 %0, %1;" : "=f"(e) : "f"(x * -1.4426950408889634f));
    float r; asm("rcp.approx.f32 %0, %1;" : "=f"(r) : "f"(1.0f + e));
    return r;
}
__device__ __forceinline__ float tanh_fast(float x){ return 2.0f * sigf(2.0f * x) - 1.0f; }
// f32x2 packed-FMA helpers (fallback path)
__device__ __forceinline__ void fma2(unsigned long long &c, const unsigned long long a, const unsigned long long b){
    asm("fma.rn.f32x2 %0, %1, %2, %0;" : "+l"(c) : "l"(a), "l"(b));
}
__device__ __forceinline__ unsigned long long dup2(float x){
    unsigned long long r; asm("mov.b64 %0, {%1, %1};" : "=l"(r) : "f"(x)); return r;
}
__device__ __forceinline__ unsigned long long pack2(float x, float y){
    unsigned long long r; asm("mov.b64 %0, {%1, %2};" : "=l"(r) : "f"(x), "f"(y)); return r;
}
__device__ __forceinline__ float2 unpack2(unsigned long long v){
    float2 r; asm("mov.b64 {%0, %1}, %2;" : "=f"(r.x), "=f"(r.y) : "l"(v)); return r;
}

#if defined(__CUDA_ARCH_FEAT_SM103_ALL)
// ---------------- tcgen05 helpers (sm_103a cubin pass only) ----------------
__device__ __forceinline__ uint32_t smem_u32(const void* p){
    uint32_t a; asm("{ .reg .u64 t; cvta.to.shared.u64 t, %1; cvt.u32.u64 %0, t; }" : "=r"(a) : "l"(p));
    return a;
}
#define MBAR_INIT(a, c) asm volatile("mbarrier.init.shared.b64 [%0], %1;" :: "r"(a), "r"(c) : "memory")
#define MBAR_ARRIVE(a)  asm volatile("mbarrier.arrive.release.cta.shared.b64 _, [%0];" :: "r"((uint32_t)(a)) : "memory")
#define MBAR_WAIT(a, ph) do { \
    uint32_t _m=(uint32_t)(a), _p=(uint32_t)(ph), _d; \
    asm volatile("{ .reg .pred p; mbarrier.try_wait.parity.acquire.cta.shared::cta.b64 p, [%1], %2; selp.b32 %0,1,0,p; }" \
        : "=r"(_d) : "r"(_m), "r"(_p) : "memory"); \
    if(!_d){ asm volatile("{ .reg .pred P1; WL_%=: mbarrier.try_wait.parity.acquire.cta.shared::cta.b64 P1, [%0], %1, 0x989680; @P1 bra.uni WD_%=; bra.uni WL_%=; WD_%=: }" \
        :: "r"(_m), "r"(_p) : "memory"); } } while(0)
#define TC_ALLOC(sa, n)  asm volatile("tcgen05.alloc.cta_group::1.sync.aligned.shared::cta.b32 [%0], %1;" :: "r"((uint32_t)(sa)), "r"((uint32_t)(n)) : "memory")
#define TC_DEALLOC(t, n) asm volatile("tcgen05.dealloc.cta_group::1.sync.aligned.b32 %0, %1;" :: "r"(t), "r"(n))
#define TC_COMMIT(a)     asm volatile("tcgen05.commit.cta_group::1.mbarrier::arrive::one.shared::cluster.b64 [%0];" :: "r"((uint32_t)(a)) : "memory")
#define TC_FENCE_AFTER() asm volatile("tcgen05.fence::after_thread_sync;" ::: "memory")
#define TC_WAIT_LD()     asm volatile("tcgen05.wait::ld.sync.aligned;" ::: "memory")
#define FENCE_ASYNC()    asm volatile("fence.proxy.async.shared::cta;" ::: "memory")
#define TC_LD_X32(r, a) \
    asm volatile("tcgen05.ld.sync.aligned.32x32b.x32.b32 " \
        "{%0,%1,%2,%3,%4,%5,%6,%7,%8,%9,%10,%11,%12,%13,%14,%15," \
        "%16,%17,%18,%19,%20,%21,%22,%23,%24,%25,%26,%27,%28,%29,%30,%31}, [%32];" \
        : "=r"((r)[0]),"=r"((r)[1]),"=r"((r)[2]),"=r"((r)[3]),"=r"((r)[4]),"=r"((r)[5]),"=r"((r)[6]),"=r"((r)[7]), \
          "=r"((r)[8]),"=r"((r)[9]),"=r"((r)[10]),"=r"((r)[11]),"=r"((r)[12]),"=r"((r)[13]),"=r"((r)[14]),"=r"((r)[15]), \
          "=r"((r)[16]),"=r"((r)[17]),"=r"((r)[18]),"=r"((r)[19]),"=r"((r)[20]),"=r"((r)[21]),"=r"((r)[22]),"=r"((r)[23]), \
          "=r"((r)[24]),"=r"((r)[25]),"=r"((r)[26]),"=r"((r)[27]),"=r"((r)[28]),"=r"((r)[29]),"=r"((r)[30]),"=r"((r)[31]) \
        : "r"(a))

__device__ __forceinline__ void mma_f16_ss(uint32_t d, uint64_t ad, uint64_t bd, uint32_t idesc, uint32_t en){
    asm volatile(
      "{\n\t.reg .pred p;\n\tsetp.ne.u32 p, %5, 0;\n\t"
      "tcgen05.mma.cta_group::1.kind::f16 [%0], %1, %2, %3, {%4, %4, %4, %4}, p;\n\t}"
      :: "r"(d), "l"(ad), "l"(bd), "r"(idesc), "r"(0u), "r"(en) : "memory");
}
// SW128 K-major descriptor: layout=2, version=1, SBO=64 (1024B 8-row group), LBO=1 (16B)
__device__ __forceinline__ uint64_t make_desc128(uint32_t addr){
    return (((uint64_t)2<<61) | ((uint64_t)1<<46) | ((uint64_t)64<<32) | ((uint64_t)1<<16))
         | ((uint64_t)(addr>>4) & 0x3FFF);
}
// cg1 f16: dtype=F32, a/b = F16 (0), M=128, N=256
static constexpr uint32_t IDESC = (1u<<4)|((256u/8)<<17)|((128u/16)<<24);
#endif

// ---------------- prep kernels (3 launches) ----------------
__global__ void k_prep_xb2(const float* __restrict__ X, const float* __restrict__ b2){
    int idx = blockIdx.x * blockDim.x + threadIdx.x;
    const int totX = NB*(TT+1)*KA0;
    if (idx < totX) {
        int k = idx % KA0;
        int r = (idx / KA0) % (TT+1);
        int b = idx / (KA0*(TT+1));
        float v = 0.0f;
        if (k < NIN && r > 0) v = X[(b*NIN + k)*TT + (r-1)];
        g_Xt[idx] = __float2half(v);
    } else {
        int c = idx - totX;
        if (c < NPAD) {
            float v = 0.0f;
            if (c < 4*HSZ) { int unit = c >> 2, g = c & 3; v = b2[g*HSZ + unit]; }
            g_b2p[c] = v;
        }
    }
}
__global__ void k_prep_w(const float* __restrict__ w1, const float* __restrict__ w2){
    size_t idx = (size_t)blockIdx.x * blockDim.x + threadIdx.x;
    const size_t tot1 = (size_t)NPAD*(2*KA0);
    const size_t tot2 = (size_t)NPAD*(2*KA1);
    if (idx < tot1) {
        int k = (int)(idx % (2*KA0));
        int n = (int)(idx / (2*KA0));
        float v = 0.0f;
        if (n < 4*HSZ) {
            int unit = n >> 2, g = n & 3;
            int ch = g*HSZ + unit;
            int tap = (k >= KA0) ? 1 : 0;
            int kk = k - tap*KA0;
            if (kk < NIN) v = w1[((size_t)ch*NIN + kk)*2 + tap];
        }
        g_W1t[idx] = __float2half(v);
    } else if (idx < tot1 + tot2) {
        size_t j = idx - tot1;
        int k = (int)(j % (2*KA1));
        int n = (int)(j / (2*KA1));
        float v = 0.0f;
        if (n < 4*HSZ) {
            int unit = n >> 2, g = n & 3;
            int ch = g*HSZ + unit;
            int tap = (k >= KA1) ? 1 : 0;
            int kk = k - tap*KA1;
            if (kk < HSZ) v = w2[((size_t)ch*HSZ + kk)*2 + tap];
        }
        g_W2t[j] = __float2half(v);
    }
}
__global__ void k_prep_hc(const float* __restrict__ hid, const float* __restrict__ cell){
    int idx = blockIdx.x * blockDim.x + threadIdx.x;
    const int totH = NB*(TT+1)*KA1;
    if (idx < totH) {
        int k = idx % KA1;
        int r = (idx / KA1) % (TT+1);
        int b = idx / (KA1*(TT+1));
        float v = 0.0f;
        if (r == 0 && k < HSZ) v = hid[b*HSZ + k];
        __half hv = __float2half(v);
        g_Ht[0][idx] = hv; g_Ht[1][idx] = hv;
    } else {
        int j = idx - totH;
        const int totC = NB*(TT+1)*HSZ;
        if (j < totC) {
            int k = j % HSZ;
            int r = (j / HSZ) % (TT+1);
            int b = j / (HSZ*(TT+1));
            float v = (r == 0) ? cell[b*HSZ + k] : 0.0f;
            g_C[0][j] = v; g_C[1][j] = v;
        }
    }
}

// ---------------- main fused GEMM + gates (cg1, M=256 x N=256 per CTA) ----------------
// Warp-specialized: 288 threads. Warps 0-7 = producers
// (LDG -> STS -> fence.proxy.async (per thread; REQUIRED) -> __syncwarp -> lane0 arrive),
// warp 8 (tid 256) = MMA issuer (wait full[s] -> 8 dispatches -> commit done[s]).
// full[s] count = 8 (one arrival per producer warp) to avoid 256-way mbar atomics.
// Single fp16 A/B, fp32 TMEM (two M=128 tiles). K-chunk = 64 fp16 (SW128).
// 3-stage smem pipeline (64KB/stage) + register double-buffer.
#define STG 65536
#define NSTG 3
#define SMEM_DYN (1024 + NSTG*STG)
#define NTHR 288

__global__ __launch_bounds__(NTHR, 1)
void k_tcmm(int mode, int prev, int cur)
{
    extern __shared__ __align__(1024) char smem[];

    const int tid = threadIdx.x;
    const int wid = tid >> 5;
    const int lane = tid & 31;

    const __half* __restrict__ Aw;
    const __half* __restrict__ Bw;
    int lda, kw, csec;
    if (mode) { Aw = g_Ht[prev]; Bw = g_W2t; lda = KA1; kw = 2*KA1; csec = 16; }
    else      { Aw = g_Xt;       Bw = g_W1t; lda = KA0; kw = 2*KA0; csec = 8; }

    const int n0 = blockIdx.x * 256;
    const int j  = blockIdx.y;             // batch index; CTA covers its 256 tokens

#if defined(__CUDA_ARCH_FEAT_SM103_ALL)
    // ======================= tcgen05 path =======================
    const uint32_t sb = smem_u32(smem);

    if (wid == 0) TC_ALLOC(sb, 512);
    if (tid == 0) {
        #pragma unroll
        for (int s = 0; s < NSTG; s++) {
            MBAR_INIT(sb + 64 + 8*s, 8);        // full[s]: one arrival per producer warp
            MBAR_INIT(sb + 128 + 8*s, 1);       // done[s]: MMA consumed stage
        }
    }
    __syncthreads();
    const uint32_t tmem = *(volatile uint32_t*)smem;

    const int nch = 2 * csec;                // 32 (mode1) or 16 (mode0), even

    if (tid < 256) {
        // ---------------- producers ----------------
        auto ldgc = [&](int c, float4 (&ra)[8], float4 (&rb)[8]) {
            const int sec = (c >= csec) ? 1 : 0;
            const int kc = (c - sec*csec) << 6;
            const int kb = sec*lda + kc;
            const size_t arow0 = (size_t)(j*(TT+1) + sec);
            #pragma unroll
            for (int it = 0; it < 8; it++) {
                const int jA = tid + (it << 8);
                const int row = jA >> 3, f = jA & 7;
                ra[it] = *(const float4*)(Aw + (arow0 + row)*lda + kc + (f << 3));
            }
            #pragma unroll
            for (int it = 0; it < 8; it++) {
                const int jB = tid + (it << 8);
                const int row = jB >> 3, f = jB & 7;
                rb[it] = *(const float4*)(Bw + (size_t)(n0 + row)*kw + kb + (f << 3));
            }
        };
        auto stsc = [&](int c, const float4 (&ra)[8], const float4 (&rb)[8]) {
            const int u = c / NSTG;
            const int s = c - u*NSTG;
            if (c >= NSTG) MBAR_WAIT(sb + 128 + 8*s, (u - 1) & 1);
            const uint32_t sbase = 1024 + s*STG;
            #pragma unroll
            for (int it = 0; it < 8; it++) {
                const int jA = tid + (it << 8);
                const int row = jA >> 3, f = jA & 7;
                uint32_t off = (uint32_t)((row << 7) + (f << 4));
                off ^= (off >> 3) & 0x70;
                *(float4*)(smem + sbase + off) = ra[it];
            }
            #pragma unroll
            for (int it = 0; it < 8; it++) {
                const int jB = tid + (it << 8);
                const int row = jB >> 3, f = jB & 7;
                uint32_t off = (uint32_t)((row << 7) + (f << 4));
                off ^= (off >> 3) & 0x70;
                *(float4*)(smem + sbase + 32768 + off) = rb[it];
            }
            FENCE_ASYNC();                   // per-thread: REQUIRED (R15 NaN without it)
            __syncwarp();
            if (lane == 0) MBAR_ARRIVE(sb + 64 + 8*s);
        };

        float4 raA[8], rbA[8], raB[8], rbB[8];
        ldgc(0, raA, rbA);
        for (int c = 0; c < nch; c += 2) {
            ldgc(c + 1, raB, rbB);          // prefetch next chunk before consuming current
            stsc(c, raA, rbA);
            if (c + 2 < nch) ldgc(c + 2, raA, rbA);
            stsc(c + 1, raB, rbB);
        }
    } else if (tid == 256) {
        // ---------------- dedicated MMA issuer ----------------
        for (int c = 0; c < nch; c++) {
            const int u = c / NSTG;
            const int s = c - u*NSTG;
            MBAR_WAIT(sb + 64 + 8*s, u & 1);
            const uint32_t sbase = 1024 + s*STG;
            const uint64_t ad = make_desc128(sb + sbase);
            const uint64_t bd = make_desc128(sb + sbase + 32768);
            #pragma unroll
            for (int h = 0; h < 2; h++) {
                const uint32_t dt = tmem + h*256;
                const uint64_t ho = (uint64_t)h*1024;    // 128 rows x 128B = 1024 x 16B units
                #pragma unroll
                for (int k = 0; k < 4; k++)
                    mma_f16_ss(dt, ad + ho + 2*k, bd + 2*k, IDESC, !(c == 0 && k == 0));
            }
            TC_COMMIT(sb + 128 + 8*s);
        }
    }

    // ---- drain: all threads wait for the last commit of every stage ----
    #pragma unroll
    for (int s = 0; s < NSTG; s++) {
        if (s < nch) {
            const int cl = s + NSTG*((nch - 1 - s)/NSTG);   // last chunk using stage s
            MBAR_WAIT(sb + 128 + 8*s, (cl/NSTG) & 1);
        }
    }
    TC_FENCE_AFTER();

    // ---- epilogue (warps 0-7): warp w -> D-half (w>>2), rows (w&3)*32+lane ----
    if (tid < 256) {
        const int half = wid >> 2;
        const int mg = j*256 + half*128 + ((wid & 3) << 5) + lane;
        const uint32_t tbase = tmem + half*256;
        if (mode == 0) {
            float* dst = g_pre + (size_t)mg * NPAD + n0;
            const float* bp = g_b2p + n0;
            #pragma unroll
            for (int nb = 0; nb < 8; nb++) {
                uint32_t d[32];
                TC_LD_X32(d, tbase + nb*32);
                TC_WAIT_LD();
                #pragma unroll
                for (int q = 0; q < 8; q++) {
                    const float4 bv = *(const float4*)(bp + nb*32 + q*4);
                    float4 o;
                    o.x = __uint_as_float(d[q*4+0]) + bv.x;
                    o.y = __uint_as_float(d[q*4+1]) + bv.y;
                    o.z = __uint_as_float(d[q*4+2]) + bv.z;
                    o.w = __uint_as_float(d[q*4+3]) + bv.w;
                    *(float4*)(dst + nb*32 + q*4) = o;
                }
            }
        } else {
            const int trow = mg & 255;
            const int bx = mg >> 8;
            const size_t crow = (size_t)(bx*(TT+1) + trow) * HSZ;
            const size_t hrow = (size_t)(bx*(TT+1) + trow + 1) * KA1;
            const float* __restrict__ Cpv = g_C[prev];
            float* __restrict__ Cnv = g_C[cur];
            __half* __restrict__ Hv = g_Ht[cur];
            const float* prow = g_pre + (size_t)mg * NPAD + n0;
            #pragma unroll
            for (int nb = 0; nb < 8; nb++) {
                const int col0 = n0 + nb*32;
                if (col0 >= 4*HSZ) continue;    // uniform across warp
                uint32_t d[32];
                TC_LD_X32(d, tbase + nb*32);
                TC_WAIT_LD();
                const int np0 = col0 >> 2;
                const float4* pr = (const float4*)(prow + nb*32);
                const float* cp = Cpv + crow + np0;
                float cbuf[8];
                union { __half b[8]; uint4 u; } Uh;
                #pragma unroll
                for (int q = 0; q < 8; q++) {
                    float4 p = pr[q];
                    float iv = __uint_as_float(d[q*4+0]) + p.x;
                    float ov = __uint_as_float(d[q*4+1]) + p.y;
                    float gv = __uint_as_float(d[q*4+2]) + p.z;
                    float fv = __uint_as_float(d[q*4+3]) + p.w;
                    float cc = sigf(fv)*cp[q] + sigf(iv)*tanh_fast(gv);
                    float h  = sigf(ov)*tanh_fast(cc);
                    cbuf[q] = cc;
                    Uh.b[q] = __float2half(h);
                }
                *(float4*)(Cnv + crow + HSZ + np0)     = make_float4(cbuf[0], cbuf[1], cbuf[2], cbuf[3]);
                *(float4*)(Cnv + crow + HSZ + np0 + 4) = make_float4(cbuf[4], cbuf[5], cbuf[6], cbuf[7]);
                *(uint4*)(Hv + hrow + np0) = Uh.u;
            }
        }
    }
    __syncthreads();
    if (wid == 0) TC_DEALLOC(tmem, 512);

#else
    // ======================= FFMA2 fallback (compute_103 PTX pass) =======================
    const int tidm = tid & 255;
    float* As = (float*)(smem + 1024);            // [2][16][132]
    float* Bs = (float*)(smem + 1024 + 16896);    // [2][16][128]

    const int tx = tidm & 15;
    const int ty = tidm >> 4;
    const int l_row = tidm >> 1;
    const int l_k8  = (tidm & 1) << 3;

    const int Ktot = 2*lda;
    const int nK = Ktot / 16;

    for (int mh = 0; mh < 2; mh++) {
        const int m0 = j*256 + mh*128;
        const int bidx = j;
        const int trow0 = mh*128;
        for (int npass = 0; npass < 2; npass++) {
            const int n0p = n0 + npass * 128;
            __syncthreads();

            unsigned long long acc[8][4];
            #pragma unroll
            for (int i = 0; i < 8; i++)
                #pragma unroll
                for (int jq = 0; jq < 4; jq++) acc[i][jq] = 0ull;

            float fa[8], fb[8];
            {
                const size_t arow = (size_t)(bidx*(TT+1) + trow0 + l_row);
                union { uint4 u; __half b[8]; } Aa, Bb2;
                Aa.u = *(const uint4*)(Aw + arow*lda + l_k8);
                #pragma unroll
                for (int jq = 0; jq < 8; jq++) fa[jq] = __half2float(Aa.b[jq]);
                Bb2.u = *(const uint4*)(Bw + (size_t)(n0p + l_row)*kw + l_k8);
                #pragma unroll
                for (int jq = 0; jq < 8; jq++) fb[jq] = __half2float(Bb2.b[jq]);
            }
            #pragma unroll
            for (int jq = 0; jq < 8; jq++) { As[(l_k8+jq)*132 + l_row] = fa[jq]; Bs[(l_k8+jq)*128 + l_row] = fb[jq]; }
            __syncthreads();

            int buf = 0;
            for (int ks = 0; ks < nK; ks++) {
                if (ks + 1 < nK) {
                    const int kg = (ks + 1) * 16;
                    const int tap = (kg >= lda) ? 1 : 0;
                    const int kc = kg - tap*lda;
                    const size_t arow = (size_t)(bidx*(TT+1) + trow0 + tap + l_row);
                    union { uint4 u; __half b[8]; } Aa, Bb2;
                    Aa.u = *(const uint4*)(Aw + arow*lda + kc + l_k8);
                    #pragma unroll
                    for (int jq = 0; jq < 8; jq++) fa[jq] = __half2float(Aa.b[jq]);
                    Bb2.u = *(const uint4*)(Bw + (size_t)(n0p + l_row)*kw + kg + l_k8);
                    #pragma unroll
                    for (int jq = 0; jq < 8; jq++) fb[jq] = __half2float(Bb2.b[jq]);
                }
                const float* Ab = As + buf*2112;
                const float* Bb = Bs + buf*2048;
                #pragma unroll
                for (int kk = 0; kk < 16; kk++) {
                    const float4 a0 = *(const float4*)(Ab + kk*132 + ty*8);
                    const float4 a1 = *(const float4*)(Ab + kk*132 + ty*8 + 4);
                    const float4 b0 = *(const float4*)(Bb + kk*128 + tx*8);
                    const float4 b1 = *(const float4*)(Bb + kk*128 + tx*8 + 4);
                    const unsigned long long bb0 = pack2(b0.x, b0.y);
                    const unsigned long long bb1 = pack2(b0.z, b0.w);
                    const unsigned long long bb2 = pack2(b1.x, b1.y);
                    const unsigned long long bb3 = pack2(b1.z, b1.w);
                    const float av[8] = {a0.x,a0.y,a0.z,a0.w,a1.x,a1.y,a1.z,a1.w};
                    #pragma unroll
                    for (int i = 0; i < 8; i++) {
                        const unsigned long long ad = dup2(av[i]);
                        fma2(acc[i][0], ad, bb0);
                        fma2(acc[i][1], ad, bb1);
                        fma2(acc[i][2], ad, bb2);
                        fma2(acc[i][3], ad, bb3);
                    }
                }
                if (ks + 1 < nK) {
                    const int nb = buf ^ 1;
                    __syncthreads();
                    #pragma unroll
                    for (int jq = 0; jq < 8; jq++) { As[nb*2112 + (l_k8+jq)*132 + l_row] = fa[jq]; Bs[nb*2048 + (l_k8+jq)*128 + l_row] = fb[jq]; }
                    __syncthreads();
                    buf = nb;
                }
            }

            if (mode == 0) {
                #pragma unroll
                for (int i = 0; i < 8; i++) {
                    const int mg = m0 + ty*8 + i;
                    float* dst = g_pre + (size_t)mg * NPAD + n0p + tx*8;
                    const float* bb = g_b2p + n0p + tx*8;
                    const float2 v0 = unpack2(acc[i][0]);
                    const float2 v1 = unpack2(acc[i][1]);
                    const float2 v2 = unpack2(acc[i][2]);
                    const float2 v3 = unpack2(acc[i][3]);
                    *(float4*)dst       = make_float4(v0.x + bb[0], v0.y + bb[1], v1.x + bb[2], v1.y + bb[3]);
                    *(float4*)(dst + 4) = make_float4(v2.x + bb[4], v2.y + bb[5], v3.x + bb[6], v3.y + bb[7]);
                }
            } else {
                const float* __restrict__ Cpv = g_C[prev];
                float* __restrict__ Cnv = g_C[cur];
                __half* __restrict__ Hv = g_Ht[cur];
                #pragma unroll
                for (int i = 0; i < 8; i++) {
                    const int mg = m0 + ty*8 + i;
                    const int trow = mg & 255;
                    const int bx = mg >> 8;
                    const float* prow = g_pre + (size_t)mg * NPAD + n0p + tx*8;
                    const float4 p0 = *(const float4*)prow;
                    const float4 p1 = *(const float4*)(prow + 4);
                    #pragma unroll
                    for (int q = 0; q < 2; q++) {
                        const int col = n0p + tx*8 + q*4;
                        if (col < 4*HSZ) {
                            const float2 va = unpack2(acc[i][2*q]);
                            const float2 vb = unpack2(acc[i][2*q + 1]);
                            const float4 p = q ? p1 : p0;
                            const float iv = va.x + p.x;
                            const float ov = va.y + p.y;
                            const float gv = vb.x + p.z;
                            const float fv = vb.y + p.w;
                            const int np = col >> 2;
                            const size_t crow = (size_t)(bx*(TT+1) + trow) * HSZ + np;
                            const float cc = sigf(fv)*Cpv[crow] + sigf(iv)*tanh_fast(gv);
                            const float h  = sigf(ov)*tanh_fast(cc);
                            Cnv[crow + HSZ] = cc;
                            const size_t ho = (size_t)(bx*(TT+1) + trow + 1) * KA1 + np;
                            Hv[ho] = __float2half(h);
                        }
                    }
                }
            }
        }
    }
#endif
}

// ---------------- output copies ----------------
__global__ void k_copy_slice(float* __restrict__ dst, int hsel, int bstride){
    int idx = blockIdx.x * blockDim.x + threadIdx.x;
    const int total = NB*TT*NOUTC;
    if (idx >= total) return;
    int c = idx % NOUTC;
    int t = (idx / NOUTC) & 255;
    int b = idx / (NOUTC*TT);
    size_t o = (size_t)(b*(TT+1) + t + 1)*KA1 + (HSZ - NOUTC) + c;
    dst[b*bstride + t*NOUTC + c] = __half2float(g_Ht[hsel][o]);
}
__global__ void k_copy_last(float* __restrict__ dh, float* __restrict__ dc, int hsel){
    int idx = blockIdx.x * blockDim.x + threadIdx.x;
    if (idx >= NB*HSZ) return;
    int b = idx / HSZ, h = idx % HSZ;
    size_t oh = (size_t)(b*(TT+1) + TT)*KA1 + h;
    size_t oc = (size_t)(b*(TT+1) + TT)*HSZ + h;
    dh[idx] = __half2float(g_Ht[hsel][oh]);
    dc[idx] = g_C[hsel][oc];
}

// ---------------- launch ----------------
extern "C" void kernel_launch(void* const* d_in, const int* in_sizes, int n_in,
                              void* d_out, int out_size)
{
    const float* X    = (const float*)d_in[0];
    const float* hid  = (const float*)d_in[1];
    const float* cell = (const float*)d_in[2];
    const float* w1   = (const float*)d_in[3];
    const float* w2   = (const float*)d_in[4];
    const float* b2   = (const float*)d_in[5];
    float* out = (float*)d_out;

    cudaFuncSetAttribute(k_tcmm, cudaFuncAttributeMaxDynamicSharedMemorySize, SMEM_DYN);

    k_prep_xb2<<<(NB*(TT+1)*KA0 + NPAD + 255)/256, 256>>>(X, b2);
    k_prep_w  <<<(int)(((size_t)NPAD*(2*KA0 + 2*KA1) + 255)/256), 256>>>(w1, w2);
    k_prep_hc <<<(NB*(TT+1)*KA1 + NB*(TT+1)*HSZ + 255)/256, 256>>>(hid, cell);

    dim3 grid(NPAD/256, NB);   // 16 x 8 = 128 CTAs, each M=256 x N=256
    k_tcmm<<<grid, NTHR, SMEM_DYN>>>(0, 0, 0);     // pre = conv1 + b2

    const int OFF_HT  = NB*TT*NOUTC;          // 819200
    const int OFF_CT  = OFF_HT + NB*HSZ;      // 827200
    const int OFF_AUX = OFF_CT + NB*HSZ;      // 835200

    int prev = 0;
    for (int i = 0; i < 40; i++) {
        int cur = prev ^ 1;
        k_tcmm<<<grid, NTHR, SMEM_DYN>>>(1, prev, cur);
        if (i == 19) {
            k_copy_slice<<<(NB*TT*NOUTC + 255)/256, 256>>>(out + OFF_AUX, cur, 2*TT*NOUTC);
        }
        if (i == 39) {
            k_copy_slice<<<(NB*TT*NOUTC + 255)/256, 256>>>(out, cur, TT*NOUTC);
            k_copy_slice<<<(NB*TT*NOUTC + 255)/256, 256>>>(out + OFF_AUX + TT*NOUTC, cur, 2*TT*NOUTC);
            k_copy_last <<<(NB*HSZ + 255)/256, 256>>>(out + OFF_HT, out + OFF_CT, cur);
        }
        prev = cur;
    }
}